// round 10
// baseline (speedup 1.0000x reference)
#include <cuda_runtime.h>
#include <cuda_bf16.h>
#include <math.h>
#include <stdint.h>

#define T_LEN 4096
#define C_DIM 2048
#define NH    16
#define NKV   4
#define HD    128
#define WW    1024
#define NB    4

// ---------------- scratch (device globals; no runtime alloc) ----------------
__device__ float g_Q[T_LEN * C_DIM];
__device__ float g_K[T_LEN * NKV * HD];
__device__ __nv_bfloat16 g_xH[T_LEN * C_DIM];
__device__ __nv_bfloat16 g_xL[T_LEN * C_DIM];
__device__ __nv_bfloat16 g_QH[T_LEN * C_DIM];
__device__ __nv_bfloat16 g_QL[T_LEN * C_DIM];
__device__ __nv_bfloat16 g_KH[T_LEN * NKV * HD];
__device__ __nv_bfloat16 g_KL[T_LEN * NKV * HD];
__device__ __nv_bfloat16 g_VH[T_LEN * NKV * HD];
__device__ __nv_bfloat16 g_VL[T_LEN * NKV * HD];
__device__ __nv_bfloat16 g_attH[T_LEN * C_DIM];
__device__ __nv_bfloat16 g_attL[T_LEN * C_DIM];
__device__ __nv_bfloat16 g_qwH[C_DIM * C_DIM];
__device__ __nv_bfloat16 g_qwL[C_DIM * C_DIM];
__device__ __nv_bfloat16 g_kwH[NKV * HD * C_DIM];
__device__ __nv_bfloat16 g_kwL[NKV * HD * C_DIM];
__device__ __nv_bfloat16 g_vwH[NKV * HD * C_DIM];
__device__ __nv_bfloat16 g_vwL[NKV * HD * C_DIM];
__device__ __nv_bfloat16 g_owH[C_DIM * C_DIM];
__device__ __nv_bfloat16 g_owL[C_DIM * C_DIM];

// ---------------- helpers -----------------------------------------------------
__device__ __forceinline__ uint32_t sptr(const void* p) {
    return (uint32_t)__cvta_generic_to_shared(p);
}
__device__ __forceinline__ void ldsm4(uint32_t& r0, uint32_t& r1, uint32_t& r2,
                                      uint32_t& r3, uint32_t a) {
    asm volatile("ldmatrix.sync.aligned.m8n8.x4.shared.b16 {%0,%1,%2,%3}, [%4];"
        : "=r"(r0), "=r"(r1), "=r"(r2), "=r"(r3) : "r"(a));
}
__device__ __forceinline__ void ldsm2(uint32_t& r0, uint32_t& r1, uint32_t a) {
    asm volatile("ldmatrix.sync.aligned.m8n8.x2.shared.b16 {%0,%1}, [%2];"
        : "=r"(r0), "=r"(r1) : "r"(a));
}
__device__ __forceinline__ void mma16816(float* c, uint32_t a0, uint32_t a1,
                                         uint32_t a2, uint32_t a3,
                                         uint32_t b0, uint32_t b1) {
    asm volatile(
        "mma.sync.aligned.m16n8k16.row.col.f32.bf16.bf16.f32 "
        "{%0,%1,%2,%3}, {%4,%5,%6,%7}, {%8,%9}, {%0,%1,%2,%3};"
        : "+f"(c[0]), "+f"(c[1]), "+f"(c[2]), "+f"(c[3])
        : "r"(a0), "r"(a1), "r"(a2), "r"(a3), "r"(b0), "r"(b1));
}
__device__ __forceinline__ uint32_t packbf(float x, float y) {
    __nv_bfloat162 v;
    v.x = __float2bfloat16(x);
    v.y = __float2bfloat16(y);
    return *(uint32_t*)&v;
}
__device__ __forceinline__ float ex2(float x) {
    float r;
    asm("ex2.approx.f32 %0, %1;" : "=f"(r) : "f"(x));
    return r;
}
#define CP_ASYNC16(dst, src) \
    asm volatile("cp.async.cg.shared.global [%0], [%1], 16;" \
        :: "r"(dst), "l"(src) : "memory")
#define CP_COMMIT() asm volatile("cp.async.commit_group;" ::: "memory")
#define CP_WAIT(n)  asm volatile("cp.async.wait_group %0;" :: "n"(n) : "memory")

// ---------------- elementwise fp32 -> bf16 hi/lo -----------------------------
__global__ __launch_bounds__(256) void split_ew(
    const float* __restrict__ src, __nv_bfloat16* __restrict__ dH,
    __nv_bfloat16* __restrict__ dL, int total)
{
    int idx = blockIdx.x * blockDim.x + threadIdx.x;
    if (idx >= total) return;
    float v = src[idx];
    __nv_bfloat16 h = __float2bfloat16(v);
    dH[idx] = h;
    dL[idx] = __float2bfloat16(v - __bfloat162float(h));
}

// ---------------- transpose + split: src[K][N] fp32 -> dst[N][K] bf16 hi/lo --
__global__ __launch_bounds__(256) void transpose_split(
    const float* __restrict__ src, __nv_bfloat16* __restrict__ dH,
    __nv_bfloat16* __restrict__ dL, int K, int N)
{
    __shared__ float t[32][33];
    const int n0 = blockIdx.x * 32;
    const int k0 = blockIdx.y * 32;
    const int tx = threadIdx.x & 31;
    const int ty = threadIdx.x >> 5;
#pragma unroll
    for (int i = 0; i < 4; i++)
        t[ty + i * 8][tx] = src[(size_t)(k0 + ty + i * 8) * N + n0 + tx];
    __syncthreads();
#pragma unroll
    for (int i = 0; i < 4; i++) {
        float v = t[tx][ty + i * 8];
        __nv_bfloat16 h = __float2bfloat16(v);
        size_t o = (size_t)(n0 + ty + i * 8) * K + k0 + tx;
        dH[o] = h;
        dL[o] = __float2bfloat16(v - __bfloat162float(h));
    }
}

// ============================================================================
// GEMM on pre-split operands with cp.async 3-stage pipeline.
// C[M,N] = A[M,K] * BT[N,K]^T, fp32 accumulate, 3 mma passes (HH, HL, LH).
// BM=BN=128, BK=32, 256 threads (8 warps, 64x32 warp tile), 1 sync/K-iter.
// ============================================================================
#define BM 128
#define BN 128
#define BK 32
#define KST 40                          // smem row stride in bf16 (80B = 5*16B)
#define TILE_ELEMS (BM * KST)           // 5120 bf16 = 10240 B
#define STAGE_ELEMS (4 * TILE_ELEMS)    // AH, AL, BH, BL
#define NSTAGE 3
#define GEMM_SMEM_BYTES (NSTAGE * STAGE_ELEMS * 2)   // 122880 B

template<int SPLIT_OUT>
__global__ __launch_bounds__(256) void gemm_p(
    const __nv_bfloat16* __restrict__ AH, const __nv_bfloat16* __restrict__ AL,
    const __nv_bfloat16* __restrict__ BH, const __nv_bfloat16* __restrict__ BL,
    float* __restrict__ C, __nv_bfloat16* __restrict__ CH,
    __nv_bfloat16* __restrict__ CL, int M, int N, int K)
{
    extern __shared__ __nv_bfloat16 smg[];

    const int tid  = threadIdx.x;
    const int lane = tid & 31;
    const int warp = tid >> 5;
    const int wm = (warp >> 2) * 64;
    const int wn = (warp & 3) * 32;
    const int row0 = blockIdx.y * BM;
    const int col0 = blockIdx.x * BN;

    // loader: thread covers row lr, two 8-elem chunks at cols lc0, lc0+8
    const int lr  = tid >> 1;                 // 0..127
    const int lc0 = (tid & 1) * 16;           // 0 or 16

    float acc[4][4][4];
#pragma unroll
    for (int a = 0; a < 4; a++)
#pragma unroll
        for (int b = 0; b < 4; b++)
#pragma unroll
            for (int cc = 0; cc < 4; cc++) acc[a][b][cc] = 0.f;

    const __nv_bfloat16* srcs[4] = {
        AH + (size_t)(row0 + lr) * K + lc0,
        AL + (size_t)(row0 + lr) * K + lc0,
        BH + (size_t)(col0 + lr) * K + lc0,
        BL + (size_t)(col0 + lr) * K + lc0 };
    const uint32_t sdst0 = sptr(smg) + (lr * KST + lc0) * 2;

    auto stage_issue = [&](int it, int stg) {
        const int kk = it * BK;
        const uint32_t sbase = sdst0 + stg * (STAGE_ELEMS * 2);
#pragma unroll
        for (int t4 = 0; t4 < 4; t4++) {
            const __nv_bfloat16* s = srcs[t4] + kk;
            uint32_t d = sbase + t4 * (TILE_ELEMS * 2);
            CP_ASYNC16(d,      s);
            CP_ASYNC16(d + 16, s + 8);
        }
        CP_COMMIT();
    };

    const int KITER = K / BK;
    stage_issue(0, 0);
    stage_issue(1, 1);

    for (int it = 0; it < KITER; it++) {
        if (it + 1 < KITER) { CP_WAIT(1); } else { CP_WAIT(0); }
        __syncthreads();
        if (it + 2 < KITER) stage_issue(it + 2, (it + 2) % NSTAGE);

        const __nv_bfloat16* st = smg + (it % NSTAGE) * STAGE_ELEMS;
        const __nv_bfloat16* aHb = st;
        const __nv_bfloat16* aLb = st + TILE_ELEMS;
        const __nv_bfloat16* bHb = st + 2 * TILE_ELEMS;
        const __nv_bfloat16* bLb = st + 3 * TILE_ELEMS;
#pragma unroll
        for (int g = 0; g < 2; g++) {
            const int arow = wm + (lane & 15);
            const int acol = g * 16 + (lane >> 4) * 8;
            const int brow = wn + (lane & 7);
            const int bcol = g * 16 + ((lane >> 3) & 1) * 8;
            uint32_t aHadr = sptr(aHb + arow * KST + acol);
            uint32_t aLadr = sptr(aLb + arow * KST + acol);
            uint32_t bHadr = sptr(bHb + brow * KST + bcol);
            uint32_t bLadr = sptr(bLb + brow * KST + bcol);

            uint32_t aH[4][4], aL[4][4], bH[4][2], bL[4][2];
#pragma unroll
            for (int mf = 0; mf < 4; mf++) {
                ldsm4(aH[mf][0], aH[mf][1], aH[mf][2], aH[mf][3],
                      aHadr + mf * 16 * KST * 2);
                ldsm4(aL[mf][0], aL[mf][1], aL[mf][2], aL[mf][3],
                      aLadr + mf * 16 * KST * 2);
            }
#pragma unroll
            for (int nf = 0; nf < 4; nf++) {
                ldsm2(bH[nf][0], bH[nf][1], bHadr + nf * 8 * KST * 2);
                ldsm2(bL[nf][0], bL[nf][1], bLadr + nf * 8 * KST * 2);
            }
#pragma unroll
            for (int mf = 0; mf < 4; mf++)
#pragma unroll
                for (int nf = 0; nf < 4; nf++) {
                    mma16816(acc[mf][nf], aH[mf][0], aH[mf][1], aH[mf][2], aH[mf][3],
                             bH[nf][0], bH[nf][1]);
                    mma16816(acc[mf][nf], aH[mf][0], aH[mf][1], aH[mf][2], aH[mf][3],
                             bL[nf][0], bL[nf][1]);
                    mma16816(acc[mf][nf], aL[mf][0], aL[mf][1], aL[mf][2], aL[mf][3],
                             bH[nf][0], bH[nf][1]);
                }
        }
    }

#pragma unroll
    for (int mf = 0; mf < 4; mf++)
#pragma unroll
        for (int nf = 0; nf < 4; nf++) {
            int m = row0 + wm + mf * 16 + (lane >> 2);
            int n = col0 + wn + nf * 8 + (lane & 3) * 2;
            if (SPLIT_OUT == 0) {
                *(float2*)(C + (size_t)m * N + n) =
                    make_float2(acc[mf][nf][0], acc[mf][nf][1]);
                *(float2*)(C + (size_t)(m + 8) * N + n) =
                    make_float2(acc[mf][nf][2], acc[mf][nf][3]);
            } else {
#pragma unroll
                for (int half = 0; half < 2; half++) {
                    float v0 = acc[mf][nf][half * 2 + 0];
                    float v1 = acc[mf][nf][half * 2 + 1];
                    uint32_t hh = packbf(v0, v1);
                    __nv_bfloat162 hv = *(__nv_bfloat162*)&hh;
                    uint32_t ll = packbf(v0 - __bfloat162float(hv.x),
                                         v1 - __bfloat162float(hv.y));
                    size_t o = (size_t)(m + half * 8) * N + n;
                    *(uint32_t*)(CH + o) = hh;
                    *(uint32_t*)(CL + o) = ll;
                }
            }
        }
}

// ---------------- RoPE + bf16 hi/lo split ------------------------------------
__global__ __launch_bounds__(256) void rope_split(
    const float* __restrict__ src, __nv_bfloat16* __restrict__ dH,
    __nv_bfloat16* __restrict__ dL, int nheads)
{
    int idx = blockIdx.x * blockDim.x + threadIdx.x;
    int total = T_LEN * nheads * 64;
    if (idx >= total) return;
    int i  = idx & 63;
    int hd = (idx >> 6) % nheads;
    int t  = idx / (64 * nheads);

    float ts  = powf(10000.0f, (float)i * (1.0f / 64.0f));
    float ang = (float)t / ts;
    float s, c;
    sincosf(ang, &s, &c);

    size_t base = ((size_t)t * nheads + hd) * HD + i;
    float a = src[base];
    float b = src[base + 64];
    float r0 = a * c - b * s;
    float r1 = b * c + a * s;

    __nv_bfloat16 h0 = __float2bfloat16(r0);
    __nv_bfloat16 h1 = __float2bfloat16(r1);
    dH[base]      = h0;
    dH[base + 64] = h1;
    dL[base]      = __float2bfloat16(r0 - __bfloat162float(h0));
    dL[base + 64] = __float2bfloat16(r1 - __bfloat162float(h1));
}

// ============================================================================
// Attention on tensor cores (validated R5/R8, unchanged)
// ============================================================================
#define QKSTRIDE 136
#define VTSTRIDE 72
#define SM_QH 0
#define SM_QL 8704
#define SM_KH 17408
#define SM_KL 26112
#define SM_VH 34816
#define SM_VL 44032
#define ATTN_SMEM_BYTES (53248 * 2)

__global__ __launch_bounds__(128) void attn_mma(
    const __nv_bfloat16* __restrict__ QH, const __nv_bfloat16* __restrict__ QL,
    const __nv_bfloat16* __restrict__ KH, const __nv_bfloat16* __restrict__ KL,
    const __nv_bfloat16* __restrict__ VH, const __nv_bfloat16* __restrict__ VL,
    __nv_bfloat16* __restrict__ attH, __nv_bfloat16* __restrict__ attL)
{
    extern __shared__ __nv_bfloat16 sa[];
    __nv_bfloat16* QsH = sa + SM_QH;
    __nv_bfloat16* QsL = sa + SM_QL;
    __nv_bfloat16* KsH = sa + SM_KH;
    __nv_bfloat16* KsL = sa + SM_KL;
    __nv_bfloat16* VtH = sa + SM_VH;
    __nv_bfloat16* VtL = sa + SM_VL;

    const int qt = blockIdx.x;
    const int h  = blockIdx.y;
    const int n  = blockIdx.z;
    const int kvh = h >> 2;
    const int p0  = qt * 64;
    const int tid  = threadIdx.x;
    const int lane = tid & 31;
    const int warp = tid >> 5;
    const int wq   = warp * 16;

    {
        int row = tid >> 1;
        int dh  = (tid & 1) * 64;
        size_t src = ((size_t)(n * WW + p0 + row)) * C_DIM + h * HD + dh;
        int dst = row * QKSTRIDE + dh;
#pragma unroll
        for (int i = 0; i < 8; i++) {
            *(uint4*)(QsH + dst + i * 8) = *(const uint4*)(QH + src + i * 8);
            *(uint4*)(QsL + dst + i * 8) = *(const uint4*)(QL + src + i * 8);
        }
    }

    float o[16][4];
#pragma unroll
    for (int dt = 0; dt < 16; dt++)
#pragma unroll
        for (int c = 0; c < 4; c++) o[dt][c] = 0.f;
    float m0 = -1e30f, m1 = -1e30f, l0 = 0.f, l1 = 0.f;

    const float SCL = 0.08838834764831845f * 1.4426950408889634f;
    const int kt0 = (n == 0) ? (16 - qt) : 0;

    for (int kt = kt0; kt <= 16; kt++) {
        const int jt  = p0 + kt * 64;
        const int ktg0 = (n - 1) * WW + jt;
        __syncthreads();

        {
            int key = tid >> 1;
            int dh  = (tid & 1) * 64;
            size_t src = ((size_t)(ktg0 + key)) * (NKV * HD) + kvh * HD + dh;
            int dst = key * QKSTRIDE + dh;
#pragma unroll
            for (int i = 0; i < 8; i++) {
                *(uint4*)(KsH + dst + i * 8) = *(const uint4*)(KH + src + i * 8);
                *(uint4*)(KsL + dst + i * 8) = *(const uint4*)(KL + src + i * 8);
            }
        }
        {
            int key = tid & 63;
            int dh  = (tid >> 6) * 64;
            size_t src = ((size_t)(ktg0 + key)) * (NKV * HD) + kvh * HD + dh;
#pragma unroll
            for (int i = 0; i < 8; i++) {
                uint4 vh = *(const uint4*)(VH + src + i * 8);
                uint4 vl = *(const uint4*)(VL + src + i * 8);
                const __nv_bfloat16* phv = (const __nv_bfloat16*)&vh;
                const __nv_bfloat16* plv = (const __nv_bfloat16*)&vl;
#pragma unroll
                for (int e = 0; e < 8; e++) {
                    VtH[(dh + i * 8 + e) * VTSTRIDE + key] = phv[e];
                    VtL[(dh + i * 8 + e) * VTSTRIDE + key] = plv[e];
                }
            }
        }
        __syncthreads();

        float s[8][4];
#pragma unroll
        for (int nt = 0; nt < 8; nt++)
#pragma unroll
            for (int c = 0; c < 4; c++) s[nt][c] = 0.f;

        const int arow = wq + (lane & 15);
        const int acolo = (lane >> 4) * 8;
        const int brow = lane & 7;
        const int bcolo = ((lane >> 3) & 1) * 8;
#pragma unroll
        for (int ks = 0; ks < 8; ks++) {
            uint32_t aH0, aH1, aH2, aH3, aL0, aL1, aL2, aL3;
            ldsm4(aH0, aH1, aH2, aH3,
                  sptr(QsH + arow * QKSTRIDE + ks * 16 + acolo));
            ldsm4(aL0, aL1, aL2, aL3,
                  sptr(QsL + arow * QKSTRIDE + ks * 16 + acolo));
#pragma unroll
            for (int nt = 0; nt < 8; nt++) {
                uint32_t bH0, bH1, bL0, bL1;
                ldsm2(bH0, bH1,
                      sptr(KsH + (nt * 8 + brow) * QKSTRIDE + ks * 16 + bcolo));
                ldsm2(bL0, bL1,
                      sptr(KsL + (nt * 8 + brow) * QKSTRIDE + ks * 16 + bcolo));
                mma16816(s[nt], aH0, aH1, aH2, aH3, bH0, bH1);
                mma16816(s[nt], aH0, aH1, aH2, aH3, bL0, bL1);
                mma16816(s[nt], aL0, aL1, aL2, aL3, bH0, bH1);
            }
        }

#pragma unroll
        for (int nt = 0; nt < 8; nt++)
#pragma unroll
            for (int c = 0; c < 4; c++) s[nt][c] *= SCL;

        if (kt == 0 || kt == 16) {
            const bool upper = (kt == 16);
            const int r0 = p0 + wq + (lane >> 2);
            const int r1 = r0 + 8;
#pragma unroll
            for (int nt = 0; nt < 8; nt++) {
                int j0 = jt + nt * 8 + (lane & 3) * 2;
#pragma unroll
                for (int c = 0; c < 2; c++) {
                    int j = j0 + c;
                    bool v0 = upper ? (j <= r0 + WW) : (j >= r0);
                    bool v1 = upper ? (j <= r1 + WW) : (j >= r1);
                    if (!v0) s[nt][c]     = -1e30f;
                    if (!v1) s[nt][c + 2] = -1e30f;
                }
            }
        }

        float nm0 = -1e30f, nm1 = -1e30f;
#pragma unroll
        for (int nt = 0; nt < 8; nt++) {
            nm0 = fmaxf(nm0, fmaxf(s[nt][0], s[nt][1]));
            nm1 = fmaxf(nm1, fmaxf(s[nt][2], s[nt][3]));
        }
#pragma unroll
        for (int off = 1; off <= 2; off <<= 1) {
            nm0 = fmaxf(nm0, __shfl_xor_sync(0xffffffffu, nm0, off));
            nm1 = fmaxf(nm1, __shfl_xor_sync(0xffffffffu, nm1, off));
        }
        nm0 = fmaxf(nm0, m0);
        nm1 = fmaxf(nm1, m1);
        float sc0 = ex2(m0 - nm0);
        float sc1 = ex2(m1 - nm1);

        uint32_t pH[8][2], pL[8][2];
        float ls0 = 0.f, ls1 = 0.f;
#pragma unroll
        for (int nt = 0; nt < 8; nt++) {
            float p00 = ex2(s[nt][0] - nm0);
            float p01 = ex2(s[nt][1] - nm0);
            float p10 = ex2(s[nt][2] - nm1);
            float p11 = ex2(s[nt][3] - nm1);
            ls0 += p00 + p01;
            ls1 += p10 + p11;
            pH[nt][0] = packbf(p00, p01);
            pH[nt][1] = packbf(p10, p11);
            __nv_bfloat162 h0 = *(__nv_bfloat162*)&pH[nt][0];
            __nv_bfloat162 h1 = *(__nv_bfloat162*)&pH[nt][1];
            pL[nt][0] = packbf(p00 - __bfloat162float(h0.x),
                               p01 - __bfloat162float(h0.y));
            pL[nt][1] = packbf(p10 - __bfloat162float(h1.x),
                               p11 - __bfloat162float(h1.y));
        }
#pragma unroll
        for (int off = 1; off <= 2; off <<= 1) {
            ls0 += __shfl_xor_sync(0xffffffffu, ls0, off);
            ls1 += __shfl_xor_sync(0xffffffffu, ls1, off);
        }
        l0 = l0 * sc0 + ls0;
        l1 = l1 * sc1 + ls1;
        m0 = nm0;
        m1 = nm1;
#pragma unroll
        for (int dt = 0; dt < 16; dt++) {
            o[dt][0] *= sc0; o[dt][1] *= sc0;
            o[dt][2] *= sc1; o[dt][3] *= sc1;
        }

#pragma unroll
        for (int ks = 0; ks < 4; ks++) {
            uint32_t aH0 = pH[2 * ks][0],     aH1 = pH[2 * ks][1];
            uint32_t aH2 = pH[2 * ks + 1][0], aH3 = pH[2 * ks + 1][1];
            uint32_t aL0 = pL[2 * ks][0],     aL1 = pL[2 * ks][1];
            uint32_t aL2 = pL[2 * ks + 1][0], aL3 = pL[2 * ks + 1][1];
#pragma unroll
            for (int dt = 0; dt < 16; dt++) {
                uint32_t bH0, bH1, bL0, bL1;
                ldsm2(bH0, bH1,
                      sptr(VtH + (dt * 8 + brow) * VTSTRIDE + ks * 16 + bcolo));
                ldsm2(bL0, bL1,
                      sptr(VtL + (dt * 8 + brow) * VTSTRIDE + ks * 16 + bcolo));
                mma16816(o[dt], aH0, aH1, aH2, aH3, bH0, bH1);
                mma16816(o[dt], aH0, aH1, aH2, aH3, bL0, bL1);
                mma16816(o[dt], aL0, aL1, aL2, aL3, bH0, bH1);
            }
        }
    }

    float inv0 = 1.f / l0;
    float inv1 = 1.f / l1;
    const int r0 = n * WW + p0 + wq + (lane >> 2);
#pragma unroll
    for (int dt = 0; dt < 16; dt++) {
        int col = h * HD + dt * 8 + (lane & 3) * 2;
#pragma unroll
        for (int half = 0; half < 2; half++) {
            float v0 = o[dt][half * 2 + 0] * (half ? inv1 : inv0);
            float v1 = o[dt][half * 2 + 1] * (half ? inv1 : inv0);
            uint32_t hh = packbf(v0, v1);
            __nv_bfloat162 hv = *(__nv_bfloat162*)&hh;
            uint32_t ll = packbf(v0 - __bfloat162float(hv.x),
                                 v1 - __bfloat162float(hv.y));
            size_t off = (size_t)(r0 + half * 8) * C_DIM + col;
            *(uint32_t*)(attH + off) = hh;
            *(uint32_t*)(attL + off) = ll;
        }
    }
}

// ---------------- launch ----------------------------------------------------
extern "C" void kernel_launch(void* const* d_in, const int* in_sizes, int n_in,
                              void* d_out, int out_size)
{
    (void)in_sizes; (void)n_in; (void)out_size;
    const float* x  = (const float*)d_in[0];
    const float* qw = (const float*)d_in[1];
    const float* kw = (const float*)d_in[2];
    const float* vw = (const float*)d_in[3];
    const float* ow = (const float*)d_in[4];
    float* out = (float*)d_out;

    float *Qp, *Kp;
    __nv_bfloat16 *xH, *xL, *QHp, *QLp, *KHp, *KLp, *VHp, *VLp, *atH, *atL;
    __nv_bfloat16 *qwH, *qwL, *kwH, *kwL, *vwH, *vwL, *owH, *owL;
    cudaGetSymbolAddress((void**)&Qp, g_Q);
    cudaGetSymbolAddress((void**)&Kp, g_K);
    cudaGetSymbolAddress((void**)&xH, g_xH);
    cudaGetSymbolAddress((void**)&xL, g_xL);
    cudaGetSymbolAddress((void**)&QHp, g_QH);
    cudaGetSymbolAddress((void**)&QLp, g_QL);
    cudaGetSymbolAddress((void**)&KHp, g_KH);
    cudaGetSymbolAddress((void**)&KLp, g_KL);
    cudaGetSymbolAddress((void**)&VHp, g_VH);
    cudaGetSymbolAddress((void**)&VLp, g_VL);
    cudaGetSymbolAddress((void**)&atH, g_attH);
    cudaGetSymbolAddress((void**)&atL, g_attL);
    cudaGetSymbolAddress((void**)&qwH, g_qwH);
    cudaGetSymbolAddress((void**)&qwL, g_qwL);
    cudaGetSymbolAddress((void**)&kwH, g_kwH);
    cudaGetSymbolAddress((void**)&kwL, g_kwL);
    cudaGetSymbolAddress((void**)&vwH, g_vwH);
    cudaGetSymbolAddress((void**)&vwL, g_vwL);
    cudaGetSymbolAddress((void**)&owH, g_owH);
    cudaGetSymbolAddress((void**)&owL, g_owL);

    cudaFuncSetAttribute(gemm_p<0>,
                         cudaFuncAttributeMaxDynamicSharedMemorySize, GEMM_SMEM_BYTES);
    cudaFuncSetAttribute(gemm_p<1>,
                         cudaFuncAttributeMaxDynamicSharedMemorySize, GEMM_SMEM_BYTES);
    cudaFuncSetAttribute(attn_mma,
                         cudaFuncAttributeMaxDynamicSharedMemorySize, ATTN_SMEM_BYTES);

    dim3 thr(256);
    // launches 1-4: preprocessing (ow transpose deferred past attention so the
    // ncu capture window — 5th launch — lands on the Q-projection GEMM)
    split_ew<<<(T_LEN * C_DIM) / 256, 256>>>(x, xH, xL, T_LEN * C_DIM);
    transpose_split<<<dim3(C_DIM / 32, C_DIM / 32), thr>>>(qw, qwH, qwL, C_DIM, C_DIM);
    transpose_split<<<dim3((NKV * HD) / 32, C_DIM / 32), thr>>>(kw, kwH, kwL, C_DIM, NKV * HD);
    transpose_split<<<dim3((NKV * HD) / 32, C_DIM / 32), thr>>>(vw, vwH, vwL, C_DIM, NKV * HD);

    // launch 5: Q projection (profiled)
    gemm_p<0><<<dim3(C_DIM / BN, T_LEN / BM), thr, GEMM_SMEM_BYTES>>>(
        xH, xL, qwH, qwL, Qp, nullptr, nullptr, T_LEN, C_DIM, C_DIM);
    gemm_p<0><<<dim3((NKV * HD) / BN, T_LEN / BM), thr, GEMM_SMEM_BYTES>>>(
        xH, xL, kwH, kwL, Kp, nullptr, nullptr, T_LEN, NKV * HD, C_DIM);
    gemm_p<1><<<dim3((NKV * HD) / BN, T_LEN / BM), thr, GEMM_SMEM_BYTES>>>(
        xH, xL, vwH, vwL, nullptr, VHp, VLp, T_LEN, NKV * HD, C_DIM);

    // RoPE + hi/lo split
    rope_split<<<(T_LEN * NH  * 64) / 256, 256>>>(Qp, QHp, QLp, NH);
    rope_split<<<(T_LEN * NKV * 64) / 256, 256>>>(Kp, KHp, KLp, NKV);

    // attention (tensor cores)
    attn_mma<<<dim3(WW / 64, NH, NB), dim3(128), ATTN_SMEM_BYTES>>>(
        QHp, QLp, KHp, KLp, VHp, VLp, atH, atL);

    // deferred ow transpose + output projection
    transpose_split<<<dim3(C_DIM / 32, C_DIM / 32), thr>>>(ow, owH, owL, C_DIM, C_DIM);
    gemm_p<0><<<dim3(C_DIM / BN, T_LEN / BM), thr, GEMM_SMEM_BYTES>>>(
        atH, atL, owH, owL, out, nullptr, nullptr, T_LEN, C_DIM, C_DIM);
}

// round 11
// speedup vs baseline: 1.2415x; 1.2415x over previous
#include <cuda_runtime.h>
#include <cuda_bf16.h>
#include <cuda_fp16.h>
#include <math.h>
#include <stdint.h>

#define T_LEN 4096
#define C_DIM 2048
#define NH    16
#define NKV   4
#define HD    128
#define WW    1024
#define NB    4

// ---------------- scratch (device globals; no runtime alloc) ----------------
__device__ float g_Q[T_LEN * C_DIM];
__device__ float g_K[T_LEN * NKV * HD];
__device__ __half g_xH[T_LEN * C_DIM];          // x fp16 hi/lo
__device__ __half g_xL[T_LEN * C_DIM];
__device__ __nv_bfloat16 g_QH[T_LEN * C_DIM];   // attention inputs: bf16 hi/lo
__device__ __nv_bfloat16 g_QL[T_LEN * C_DIM];
__device__ __nv_bfloat16 g_KH[T_LEN * NKV * HD];
__device__ __nv_bfloat16 g_KL[T_LEN * NKV * HD];
__device__ __nv_bfloat16 g_VH[T_LEN * NKV * HD];
__device__ __nv_bfloat16 g_VL[T_LEN * NKV * HD];
__device__ __half g_attH[T_LEN * C_DIM];        // attention output: fp16 hi/lo
__device__ __half g_attL[T_LEN * C_DIM];
// transposed weights W^T [N][K], single fp16
__device__ __half g_qwT[C_DIM * C_DIM];
__device__ __half g_kwT[NKV * HD * C_DIM];
__device__ __half g_vwT[NKV * HD * C_DIM];
__device__ __half g_owT[C_DIM * C_DIM];

// ---------------- helpers -----------------------------------------------------
__device__ __forceinline__ uint32_t sptr(const void* p) {
    return (uint32_t)__cvta_generic_to_shared(p);
}
__device__ __forceinline__ void ldsm4(uint32_t& r0, uint32_t& r1, uint32_t& r2,
                                      uint32_t& r3, uint32_t a) {
    asm volatile("ldmatrix.sync.aligned.m8n8.x4.shared.b16 {%0,%1,%2,%3}, [%4];"
        : "=r"(r0), "=r"(r1), "=r"(r2), "=r"(r3) : "r"(a));
}
__device__ __forceinline__ void ldsm2(uint32_t& r0, uint32_t& r1, uint32_t a) {
    asm volatile("ldmatrix.sync.aligned.m8n8.x2.shared.b16 {%0,%1}, [%2];"
        : "=r"(r0), "=r"(r1) : "r"(a));
}
// bf16 mma (attention)
__device__ __forceinline__ void mma_bf(float* c, uint32_t a0, uint32_t a1,
                                       uint32_t a2, uint32_t a3,
                                       uint32_t b0, uint32_t b1) {
    asm volatile(
        "mma.sync.aligned.m16n8k16.row.col.f32.bf16.bf16.f32 "
        "{%0,%1,%2,%3}, {%4,%5,%6,%7}, {%8,%9}, {%0,%1,%2,%3};"
        : "+f"(c[0]), "+f"(c[1]), "+f"(c[2]), "+f"(c[3])
        : "r"(a0), "r"(a1), "r"(a2), "r"(a3), "r"(b0), "r"(b1));
}
// fp16 mma (projections)
__device__ __forceinline__ void mma_hf(float* c, uint32_t a0, uint32_t a1,
                                       uint32_t a2, uint32_t a3,
                                       uint32_t b0, uint32_t b1) {
    asm volatile(
        "mma.sync.aligned.m16n8k16.row.col.f32.f16.f16.f32 "
        "{%0,%1,%2,%3}, {%4,%5,%6,%7}, {%8,%9}, {%0,%1,%2,%3};"
        : "+f"(c[0]), "+f"(c[1]), "+f"(c[2]), "+f"(c[3])
        : "r"(a0), "r"(a1), "r"(a2), "r"(a3), "r"(b0), "r"(b1));
}
__device__ __forceinline__ uint32_t packbf(float x, float y) {
    __nv_bfloat162 v;
    v.x = __float2bfloat16(x);
    v.y = __float2bfloat16(y);
    return *(uint32_t*)&v;
}
__device__ __forceinline__ uint32_t packhf(float x, float y) {
    __half2 v;
    v.x = __float2half_rn(x);
    v.y = __float2half_rn(y);
    return *(uint32_t*)&v;
}
__device__ __forceinline__ float ex2(float x) {
    float r;
    asm("ex2.approx.f32 %0, %1;" : "=f"(r) : "f"(x));
    return r;
}
#define CP_ASYNC16(dst, src) \
    asm volatile("cp.async.cg.shared.global [%0], [%1], 16;" \
        :: "r"(dst), "l"(src) : "memory")
#define CP_COMMIT() asm volatile("cp.async.commit_group;" ::: "memory")
#define CP_WAIT(n)  asm volatile("cp.async.wait_group %0;" :: "n"(n) : "memory")

// ---------------- elementwise fp32 -> fp16 hi/lo -----------------------------
__global__ __launch_bounds__(256) void split_ew_h(
    const float* __restrict__ src, __half* __restrict__ dH,
    __half* __restrict__ dL, int total)
{
    int idx = blockIdx.x * blockDim.x + threadIdx.x;
    if (idx >= total) return;
    float v = src[idx];
    __half h = __float2half_rn(v);
    dH[idx] = h;
    dL[idx] = __float2half_rn(v - __half2float(h));
}

// ---------------- transpose: src[K][N] fp32 -> dst[N][K] fp16 ----------------
__global__ __launch_bounds__(256) void transpose_h(
    const float* __restrict__ src, __half* __restrict__ dst, int K, int N)
{
    __shared__ float t[32][33];
    const int n0 = blockIdx.x * 32;
    const int k0 = blockIdx.y * 32;
    const int tx = threadIdx.x & 31;
    const int ty = threadIdx.x >> 5;
#pragma unroll
    for (int i = 0; i < 4; i++)
        t[ty + i * 8][tx] = src[(size_t)(k0 + ty + i * 8) * N + n0 + tx];
    __syncthreads();
#pragma unroll
    for (int i = 0; i < 4; i++)
        dst[(size_t)(n0 + ty + i * 8) * K + k0 + tx] =
            __float2half_rn(t[tx][ty + i * 8]);
}

// ============================================================================
// fp16 2-pass GEMM: C[M,N] = (Ah + Al)[M,K] * BT[N,K]^T, fp32 accumulate.
// cp.async 3-stage pipeline. BM=BN=128, BK=32, 256 threads, 64x32 warp tile.
// SPLIT_OUT=0: fp32 C.  SPLIT_OUT=1: bf16 CH/CL (attention V format).
// ============================================================================
#define BM 128
#define BN 128
#define BK 32
#define KST 40
#define TILE_ELEMS (BM * KST)           // 5120 halves = 10240 B
#define STAGE_ELEMS (3 * TILE_ELEMS)    // Ah, Al, B
#define NSTAGE 3
#define GEMM_SMEM_BYTES (NSTAGE * STAGE_ELEMS * 2)   // 92160 B

template<int SPLIT_OUT>
__global__ __launch_bounds__(256) void gemm_h2(
    const __half* __restrict__ AH, const __half* __restrict__ AL,
    const __half* __restrict__ BT,
    float* __restrict__ C, __nv_bfloat16* __restrict__ CH,
    __nv_bfloat16* __restrict__ CL, int M, int N, int K)
{
    extern __shared__ __half smg[];

    const int tid  = threadIdx.x;
    const int lane = tid & 31;
    const int warp = tid >> 5;
    const int wm = (warp >> 2) * 64;
    const int wn = (warp & 3) * 32;
    const int row0 = blockIdx.y * BM;
    const int col0 = blockIdx.x * BN;

    const int lr  = tid >> 1;
    const int lc0 = (tid & 1) * 16;

    float acc[4][4][4];
#pragma unroll
    for (int a = 0; a < 4; a++)
#pragma unroll
        for (int b = 0; b < 4; b++)
#pragma unroll
            for (int cc = 0; cc < 4; cc++) acc[a][b][cc] = 0.f;

    const __half* srcs[3] = {
        AH + (size_t)(row0 + lr) * K + lc0,
        AL + (size_t)(row0 + lr) * K + lc0,
        BT + (size_t)(col0 + lr) * K + lc0 };
    const uint32_t sdst0 = sptr(smg) + (lr * KST + lc0) * 2;

    auto stage_issue = [&](int it, int stg) {
        const int kk = it * BK;
        const uint32_t sbase = sdst0 + stg * (STAGE_ELEMS * 2);
#pragma unroll
        for (int t3 = 0; t3 < 3; t3++) {
            const __half* s = srcs[t3] + kk;
            uint32_t d = sbase + t3 * (TILE_ELEMS * 2);
            CP_ASYNC16(d,      s);
            CP_ASYNC16(d + 16, s + 8);
        }
        CP_COMMIT();
    };

    const int KITER = K / BK;
    stage_issue(0, 0);
    stage_issue(1, 1);

    for (int it = 0; it < KITER; it++) {
        if (it + 1 < KITER) { CP_WAIT(1); } else { CP_WAIT(0); }
        __syncthreads();
        if (it + 2 < KITER) stage_issue(it + 2, (it + 2) % NSTAGE);

        const __half* st = smg + (it % NSTAGE) * STAGE_ELEMS;
        const __half* aHb = st;
        const __half* aLb = st + TILE_ELEMS;
        const __half* bTb = st + 2 * TILE_ELEMS;
#pragma unroll
        for (int g = 0; g < 2; g++) {
            const int arow = wm + (lane & 15);
            const int acol = g * 16 + (lane >> 4) * 8;
            const int brow = wn + (lane & 7);
            const int bcol = g * 16 + ((lane >> 3) & 1) * 8;
            uint32_t aHadr = sptr(aHb + arow * KST + acol);
            uint32_t aLadr = sptr(aLb + arow * KST + acol);
            uint32_t bTadr = sptr(bTb + brow * KST + bcol);

            uint32_t aH[4][4], aL[4][4], bT[4][2];
#pragma unroll
            for (int mf = 0; mf < 4; mf++) {
                ldsm4(aH[mf][0], aH[mf][1], aH[mf][2], aH[mf][3],
                      aHadr + mf * 16 * KST * 2);
                ldsm4(aL[mf][0], aL[mf][1], aL[mf][2], aL[mf][3],
                      aLadr + mf * 16 * KST * 2);
            }
#pragma unroll
            for (int nf = 0; nf < 4; nf++)
                ldsm2(bT[nf][0], bT[nf][1], bTadr + nf * 8 * KST * 2);
#pragma unroll
            for (int mf = 0; mf < 4; mf++)
#pragma unroll
                for (int nf = 0; nf < 4; nf++) {
                    mma_hf(acc[mf][nf], aH[mf][0], aH[mf][1], aH[mf][2], aH[mf][3],
                           bT[nf][0], bT[nf][1]);
                    mma_hf(acc[mf][nf], aL[mf][0], aL[mf][1], aL[mf][2], aL[mf][3],
                           bT[nf][0], bT[nf][1]);
                }
        }
    }

#pragma unroll
    for (int mf = 0; mf < 4; mf++)
#pragma unroll
        for (int nf = 0; nf < 4; nf++) {
            int m = row0 + wm + mf * 16 + (lane >> 2);
            int n = col0 + wn + nf * 8 + (lane & 3) * 2;
            if (SPLIT_OUT == 0) {
                *(float2*)(C + (size_t)m * N + n) =
                    make_float2(acc[mf][nf][0], acc[mf][nf][1]);
                *(float2*)(C + (size_t)(m + 8) * N + n) =
                    make_float2(acc[mf][nf][2], acc[mf][nf][3]);
            } else {
#pragma unroll
                for (int half = 0; half < 2; half++) {
                    float v0 = acc[mf][nf][half * 2 + 0];
                    float v1 = acc[mf][nf][half * 2 + 1];
                    uint32_t hh = packbf(v0, v1);
                    __nv_bfloat162 hv = *(__nv_bfloat162*)&hh;
                    uint32_t ll = packbf(v0 - __bfloat162float(hv.x),
                                         v1 - __bfloat162float(hv.y));
                    size_t o = (size_t)(m + half * 8) * N + n;
                    *(uint32_t*)(CH + o) = hh;
                    *(uint32_t*)(CL + o) = ll;
                }
            }
        }
}

// ---------------- RoPE + bf16 hi/lo split (attention inputs) -----------------
__global__ __launch_bounds__(256) void rope_split(
    const float* __restrict__ src, __nv_bfloat16* __restrict__ dH,
    __nv_bfloat16* __restrict__ dL, int nheads)
{
    int idx = blockIdx.x * blockDim.x + threadIdx.x;
    int total = T_LEN * nheads * 64;
    if (idx >= total) return;
    int i  = idx & 63;
    int hd = (idx >> 6) % nheads;
    int t  = idx / (64 * nheads);

    float ts  = powf(10000.0f, (float)i * (1.0f / 64.0f));
    float ang = (float)t / ts;
    float s, c;
    sincosf(ang, &s, &c);

    size_t base = ((size_t)t * nheads + hd) * HD + i;
    float a = src[base];
    float b = src[base + 64];
    float r0 = a * c - b * s;
    float r1 = b * c + a * s;

    __nv_bfloat16 h0 = __float2bfloat16(r0);
    __nv_bfloat16 h1 = __float2bfloat16(r1);
    dH[base]      = h0;
    dH[base + 64] = h1;
    dL[base]      = __float2bfloat16(r0 - __bfloat162float(h0));
    dL[base + 64] = __float2bfloat16(r1 - __bfloat162float(h1));
}

// ============================================================================
// Attention on tensor cores (validated); epilogue writes fp16 hi/lo.
// ============================================================================
#define QKSTRIDE 136
#define VTSTRIDE 72
#define SM_QH 0
#define SM_QL 8704
#define SM_KH 17408
#define SM_KL 26112
#define SM_VH 34816
#define SM_VL 44032
#define ATTN_SMEM_BYTES (53248 * 2)

__global__ __launch_bounds__(128) void attn_mma(
    const __nv_bfloat16* __restrict__ QH, const __nv_bfloat16* __restrict__ QL,
    const __nv_bfloat16* __restrict__ KH, const __nv_bfloat16* __restrict__ KL,
    const __nv_bfloat16* __restrict__ VH, const __nv_bfloat16* __restrict__ VL,
    __half* __restrict__ attH, __half* __restrict__ attL)
{
    extern __shared__ __nv_bfloat16 sa[];
    __nv_bfloat16* QsH = sa + SM_QH;
    __nv_bfloat16* QsL = sa + SM_QL;
    __nv_bfloat16* KsH = sa + SM_KH;
    __nv_bfloat16* KsL = sa + SM_KL;
    __nv_bfloat16* VtH = sa + SM_VH;
    __nv_bfloat16* VtL = sa + SM_VL;

    const int qt = blockIdx.x;
    const int h  = blockIdx.y;
    const int n  = blockIdx.z;
    const int kvh = h >> 2;
    const int p0  = qt * 64;
    const int tid  = threadIdx.x;
    const int lane = tid & 31;
    const int warp = tid >> 5;
    const int wq   = warp * 16;

    {
        int row = tid >> 1;
        int dh  = (tid & 1) * 64;
        size_t src = ((size_t)(n * WW + p0 + row)) * C_DIM + h * HD + dh;
        int dst = row * QKSTRIDE + dh;
#pragma unroll
        for (int i = 0; i < 8; i++) {
            *(uint4*)(QsH + dst + i * 8) = *(const uint4*)(QH + src + i * 8);
            *(uint4*)(QsL + dst + i * 8) = *(const uint4*)(QL + src + i * 8);
        }
    }

    float o[16][4];
#pragma unroll
    for (int dt = 0; dt < 16; dt++)
#pragma unroll
        for (int c = 0; c < 4; c++) o[dt][c] = 0.f;
    float m0 = -1e30f, m1 = -1e30f, l0 = 0.f, l1 = 0.f;

    const float SCL = 0.08838834764831845f * 1.4426950408889634f;
    const int kt0 = (n == 0) ? (16 - qt) : 0;

    for (int kt = kt0; kt <= 16; kt++) {
        const int jt  = p0 + kt * 64;
        const int ktg0 = (n - 1) * WW + jt;
        __syncthreads();

        {
            int key = tid >> 1;
            int dh  = (tid & 1) * 64;
            size_t src = ((size_t)(ktg0 + key)) * (NKV * HD) + kvh * HD + dh;
            int dst = key * QKSTRIDE + dh;
#pragma unroll
            for (int i = 0; i < 8; i++) {
                *(uint4*)(KsH + dst + i * 8) = *(const uint4*)(KH + src + i * 8);
                *(uint4*)(KsL + dst + i * 8) = *(const uint4*)(KL + src + i * 8);
            }
        }
        {
            int key = tid & 63;
            int dh  = (tid >> 6) * 64;
            size_t src = ((size_t)(ktg0 + key)) * (NKV * HD) + kvh * HD + dh;
#pragma unroll
            for (int i = 0; i < 8; i++) {
                uint4 vh = *(const uint4*)(VH + src + i * 8);
                uint4 vl = *(const uint4*)(VL + src + i * 8);
                const __nv_bfloat16* phv = (const __nv_bfloat16*)&vh;
                const __nv_bfloat16* plv = (const __nv_bfloat16*)&vl;
#pragma unroll
                for (int e = 0; e < 8; e++) {
                    VtH[(dh + i * 8 + e) * VTSTRIDE + key] = phv[e];
                    VtL[(dh + i * 8 + e) * VTSTRIDE + key] = plv[e];
                }
            }
        }
        __syncthreads();

        float s[8][4];
#pragma unroll
        for (int nt = 0; nt < 8; nt++)
#pragma unroll
            for (int c = 0; c < 4; c++) s[nt][c] = 0.f;

        const int arow = wq + (lane & 15);
        const int acolo = (lane >> 4) * 8;
        const int brow = lane & 7;
        const int bcolo = ((lane >> 3) & 1) * 8;
#pragma unroll
        for (int ks = 0; ks < 8; ks++) {
            uint32_t aH0, aH1, aH2, aH3, aL0, aL1, aL2, aL3;
            ldsm4(aH0, aH1, aH2, aH3,
                  sptr(QsH + arow * QKSTRIDE + ks * 16 + acolo));
            ldsm4(aL0, aL1, aL2, aL3,
                  sptr(QsL + arow * QKSTRIDE + ks * 16 + acolo));
#pragma unroll
            for (int nt = 0; nt < 8; nt++) {
                uint32_t bH0, bH1, bL0, bL1;
                ldsm2(bH0, bH1,
                      sptr(KsH + (nt * 8 + brow) * QKSTRIDE + ks * 16 + bcolo));
                ldsm2(bL0, bL1,
                      sptr(KsL + (nt * 8 + brow) * QKSTRIDE + ks * 16 + bcolo));
                mma_bf(s[nt], aH0, aH1, aH2, aH3, bH0, bH1);
                mma_bf(s[nt], aH0, aH1, aH2, aH3, bL0, bL1);
                mma_bf(s[nt], aL0, aL1, aL2, aL3, bH0, bH1);
            }
        }

#pragma unroll
        for (int nt = 0; nt < 8; nt++)
#pragma unroll
            for (int c = 0; c < 4; c++) s[nt][c] *= SCL;

        if (kt == 0 || kt == 16) {
            const bool upper = (kt == 16);
            const int r0 = p0 + wq + (lane >> 2);
            const int r1 = r0 + 8;
#pragma unroll
            for (int nt = 0; nt < 8; nt++) {
                int j0 = jt + nt * 8 + (lane & 3) * 2;
#pragma unroll
                for (int c = 0; c < 2; c++) {
                    int j = j0 + c;
                    bool v0 = upper ? (j <= r0 + WW) : (j >= r0);
                    bool v1 = upper ? (j <= r1 + WW) : (j >= r1);
                    if (!v0) s[nt][c]     = -1e30f;
                    if (!v1) s[nt][c + 2] = -1e30f;
                }
            }
        }

        float nm0 = -1e30f, nm1 = -1e30f;
#pragma unroll
        for (int nt = 0; nt < 8; nt++) {
            nm0 = fmaxf(nm0, fmaxf(s[nt][0], s[nt][1]));
            nm1 = fmaxf(nm1, fmaxf(s[nt][2], s[nt][3]));
        }
#pragma unroll
        for (int off = 1; off <= 2; off <<= 1) {
            nm0 = fmaxf(nm0, __shfl_xor_sync(0xffffffffu, nm0, off));
            nm1 = fmaxf(nm1, __shfl_xor_sync(0xffffffffu, nm1, off));
        }
        nm0 = fmaxf(nm0, m0);
        nm1 = fmaxf(nm1, m1);
        float sc0 = ex2(m0 - nm0);
        float sc1 = ex2(m1 - nm1);

        uint32_t pH[8][2], pL[8][2];
        float ls0 = 0.f, ls1 = 0.f;
#pragma unroll
        for (int nt = 0; nt < 8; nt++) {
            float p00 = ex2(s[nt][0] - nm0);
            float p01 = ex2(s[nt][1] - nm0);
            float p10 = ex2(s[nt][2] - nm1);
            float p11 = ex2(s[nt][3] - nm1);
            ls0 += p00 + p01;
            ls1 += p10 + p11;
            pH[nt][0] = packbf(p00, p01);
            pH[nt][1] = packbf(p10, p11);
            __nv_bfloat162 h0 = *(__nv_bfloat162*)&pH[nt][0];
            __nv_bfloat162 h1 = *(__nv_bfloat162*)&pH[nt][1];
            pL[nt][0] = packbf(p00 - __bfloat162float(h0.x),
                               p01 - __bfloat162float(h0.y));
            pL[nt][1] = packbf(p10 - __bfloat162float(h1.x),
                               p11 - __bfloat162float(h1.y));
        }
#pragma unroll
        for (int off = 1; off <= 2; off <<= 1) {
            ls0 += __shfl_xor_sync(0xffffffffu, ls0, off);
            ls1 += __shfl_xor_sync(0xffffffffu, ls1, off);
        }
        l0 = l0 * sc0 + ls0;
        l1 = l1 * sc1 + ls1;
        m0 = nm0;
        m1 = nm1;
#pragma unroll
        for (int dt = 0; dt < 16; dt++) {
            o[dt][0] *= sc0; o[dt][1] *= sc0;
            o[dt][2] *= sc1; o[dt][3] *= sc1;
        }

#pragma unroll
        for (int ks = 0; ks < 4; ks++) {
            uint32_t aH0 = pH[2 * ks][0],     aH1 = pH[2 * ks][1];
            uint32_t aH2 = pH[2 * ks + 1][0], aH3 = pH[2 * ks + 1][1];
            uint32_t aL0 = pL[2 * ks][0],     aL1 = pL[2 * ks][1];
            uint32_t aL2 = pL[2 * ks + 1][0], aL3 = pL[2 * ks + 1][1];
#pragma unroll
            for (int dt = 0; dt < 16; dt++) {
                uint32_t bH0, bH1, bL0, bL1;
                ldsm2(bH0, bH1,
                      sptr(VtH + (dt * 8 + brow) * VTSTRIDE + ks * 16 + bcolo));
                ldsm2(bL0, bL1,
                      sptr(VtL + (dt * 8 + brow) * VTSTRIDE + ks * 16 + bcolo));
                mma_bf(o[dt], aH0, aH1, aH2, aH3, bH0, bH1);
                mma_bf(o[dt], aH0, aH1, aH2, aH3, bL0, bL1);
                mma_bf(o[dt], aL0, aL1, aL2, aL3, bH0, bH1);
            }
        }
    }

    // ---- normalize + split-store fp16 hi/lo (for fp16 out-proj) ----
    float inv0 = 1.f / l0;
    float inv1 = 1.f / l1;
    const int r0 = n * WW + p0 + wq + (lane >> 2);
#pragma unroll
    for (int dt = 0; dt < 16; dt++) {
        int col = h * HD + dt * 8 + (lane & 3) * 2;
#pragma unroll
        for (int half = 0; half < 2; half++) {
            float v0 = o[dt][half * 2 + 0] * (half ? inv1 : inv0);
            float v1 = o[dt][half * 2 + 1] * (half ? inv1 : inv0);
            uint32_t hh = packhf(v0, v1);
            __half2 hv = *(__half2*)&hh;
            uint32_t ll = packhf(v0 - __half2float(hv.x),
                                 v1 - __half2float(hv.y));
            size_t off = (size_t)(r0 + half * 8) * C_DIM + col;
            *(uint32_t*)(attH + off) = hh;
            *(uint32_t*)(attL + off) = ll;
        }
    }
}

// ---------------- launch ----------------------------------------------------
extern "C" void kernel_launch(void* const* d_in, const int* in_sizes, int n_in,
                              void* d_out, int out_size)
{
    (void)in_sizes; (void)n_in; (void)out_size;
    const float* x  = (const float*)d_in[0];
    const float* qw = (const float*)d_in[1];
    const float* kw = (const float*)d_in[2];
    const float* vw = (const float*)d_in[3];
    const float* ow = (const float*)d_in[4];
    float* out = (float*)d_out;

    float *Qp, *Kp;
    __half *xH, *xL, *atH, *atL, *qwT, *kwT, *vwT, *owT;
    __nv_bfloat16 *QHp, *QLp, *KHp, *KLp, *VHp, *VLp;
    cudaGetSymbolAddress((void**)&Qp, g_Q);
    cudaGetSymbolAddress((void**)&Kp, g_K);
    cudaGetSymbolAddress((void**)&xH, g_xH);
    cudaGetSymbolAddress((void**)&xL, g_xL);
    cudaGetSymbolAddress((void**)&QHp, g_QH);
    cudaGetSymbolAddress((void**)&QLp, g_QL);
    cudaGetSymbolAddress((void**)&KHp, g_KH);
    cudaGetSymbolAddress((void**)&KLp, g_KL);
    cudaGetSymbolAddress((void**)&VHp, g_VH);
    cudaGetSymbolAddress((void**)&VLp, g_VL);
    cudaGetSymbolAddress((void**)&atH, g_attH);
    cudaGetSymbolAddress((void**)&atL, g_attL);
    cudaGetSymbolAddress((void**)&qwT, g_qwT);
    cudaGetSymbolAddress((void**)&kwT, g_kwT);
    cudaGetSymbolAddress((void**)&vwT, g_vwT);
    cudaGetSymbolAddress((void**)&owT, g_owT);

    cudaFuncSetAttribute(gemm_h2<0>,
                         cudaFuncAttributeMaxDynamicSharedMemorySize, GEMM_SMEM_BYTES);
    cudaFuncSetAttribute(gemm_h2<1>,
                         cudaFuncAttributeMaxDynamicSharedMemorySize, GEMM_SMEM_BYTES);
    cudaFuncSetAttribute(attn_mma,
                         cudaFuncAttributeMaxDynamicSharedMemorySize, ATTN_SMEM_BYTES);

    dim3 thr(256);
    // preprocessing
    split_ew_h<<<(T_LEN * C_DIM) / 256, 256>>>(x, xH, xL, T_LEN * C_DIM);
    transpose_h<<<dim3(C_DIM / 32, C_DIM / 32), thr>>>(qw, qwT, C_DIM, C_DIM);
    transpose_h<<<dim3((NKV * HD) / 32, C_DIM / 32), thr>>>(kw, kwT, C_DIM, NKV * HD);
    transpose_h<<<dim3((NKV * HD) / 32, C_DIM / 32), thr>>>(vw, vwT, C_DIM, NKV * HD);

    // QKV projections (fp16 2-pass)
    gemm_h2<0><<<dim3(C_DIM / BN, T_LEN / BM), thr, GEMM_SMEM_BYTES>>>(
        xH, xL, qwT, Qp, nullptr, nullptr, T_LEN, C_DIM, C_DIM);
    gemm_h2<0><<<dim3((NKV * HD) / BN, T_LEN / BM), thr, GEMM_SMEM_BYTES>>>(
        xH, xL, kwT, Kp, nullptr, nullptr, T_LEN, NKV * HD, C_DIM);
    gemm_h2<1><<<dim3((NKV * HD) / BN, T_LEN / BM), thr, GEMM_SMEM_BYTES>>>(
        xH, xL, vwT, nullptr, VHp, VLp, T_LEN, NKV * HD, C_DIM);

    // RoPE + bf16 hi/lo split (attention inputs)
    rope_split<<<(T_LEN * NH  * 64) / 256, 256>>>(Qp, QHp, QLp, NH);
    rope_split<<<(T_LEN * NKV * 64) / 256, 256>>>(Kp, KHp, KLp, NKV);

    // attention (bf16 3-pass, validated) -> fp16 hi/lo
    attn_mma<<<dim3(WW / 64, NH, NB), dim3(128), ATTN_SMEM_BYTES>>>(
        QHp, QLp, KHp, KLp, VHp, VLp, atH, atL);

    // out projection (fp16 2-pass)
    transpose_h<<<dim3(C_DIM / 32, C_DIM / 32), thr>>>(ow, owT, C_DIM, C_DIM);
    gemm_h2<0><<<dim3(C_DIM / BN, T_LEN / BM), thr, GEMM_SMEM_BYTES>>>(
        atH, atL, owT, out, nullptr, nullptr, T_LEN, C_DIM, C_DIM);
}

// round 12
// speedup vs baseline: 1.5821x; 1.2743x over previous
#include <cuda_runtime.h>
#include <cuda_bf16.h>
#include <cuda_fp16.h>
#include <math.h>
#include <stdint.h>

#define T_LEN 4096
#define C_DIM 2048
#define NH    16
#define NKV   4
#define HD    128
#define WW    1024
#define NB    4

// ---------------- scratch (device globals; no runtime alloc) ----------------
__device__ float g_Q[T_LEN * C_DIM];
__device__ float g_K[T_LEN * NKV * HD];
__device__ float g_sin[T_LEN * 64];
__device__ float g_cos[T_LEN * 64];
__device__ __half g_xH[T_LEN * C_DIM];          // x fp16 hi/lo
__device__ __half g_xL[T_LEN * C_DIM];
__device__ __half g_QH[T_LEN * C_DIM];          // Q fp16 hi/lo (post-rope)
__device__ __half g_QL[T_LEN * C_DIM];
__device__ __half g_Ks[T_LEN * NKV * HD];       // K single fp16 (post-rope)
__device__ __half g_Vs[T_LEN * NKV * HD];       // V single fp16
__device__ __half g_attH[T_LEN * C_DIM];        // attention out fp16 hi/lo
__device__ __half g_attL[T_LEN * C_DIM];
// transposed weights W^T [N][K], single fp16
__device__ __half g_qwT[C_DIM * C_DIM];
__device__ __half g_kwT[NKV * HD * C_DIM];
__device__ __half g_vwT[NKV * HD * C_DIM];
__device__ __half g_owT[C_DIM * C_DIM];

// ---------------- helpers -----------------------------------------------------
__device__ __forceinline__ uint32_t sptr(const void* p) {
    return (uint32_t)__cvta_generic_to_shared(p);
}
__device__ __forceinline__ void ldsm4(uint32_t& r0, uint32_t& r1, uint32_t& r2,
                                      uint32_t& r3, uint32_t a) {
    asm volatile("ldmatrix.sync.aligned.m8n8.x4.shared.b16 {%0,%1,%2,%3}, [%4];"
        : "=r"(r0), "=r"(r1), "=r"(r2), "=r"(r3) : "r"(a));
}
__device__ __forceinline__ void ldsm2(uint32_t& r0, uint32_t& r1, uint32_t a) {
    asm volatile("ldmatrix.sync.aligned.m8n8.x2.shared.b16 {%0,%1}, [%2];"
        : "=r"(r0), "=r"(r1) : "r"(a));
}
__device__ __forceinline__ void mma_hf(float* c, uint32_t a0, uint32_t a1,
                                       uint32_t a2, uint32_t a3,
                                       uint32_t b0, uint32_t b1) {
    asm volatile(
        "mma.sync.aligned.m16n8k16.row.col.f32.f16.f16.f32 "
        "{%0,%1,%2,%3}, {%4,%5,%6,%7}, {%8,%9}, {%0,%1,%2,%3};"
        : "+f"(c[0]), "+f"(c[1]), "+f"(c[2]), "+f"(c[3])
        : "r"(a0), "r"(a1), "r"(a2), "r"(a3), "r"(b0), "r"(b1));
}
__device__ __forceinline__ uint32_t packhf(float x, float y) {
    __half2 v;
    v.x = __float2half_rn(x);
    v.y = __float2half_rn(y);
    return *(uint32_t*)&v;
}
__device__ __forceinline__ float ex2(float x) {
    float r;
    asm("ex2.approx.f32 %0, %1;" : "=f"(r) : "f"(x));
    return r;
}
#define CP_ASYNC16(dst, src) \
    asm volatile("cp.async.cg.shared.global [%0], [%1], 16;" \
        :: "r"(dst), "l"(src) : "memory")
#define CP_COMMIT() asm volatile("cp.async.commit_group;" ::: "memory")
#define CP_WAIT(n)  asm volatile("cp.async.wait_group %0;" :: "n"(n) : "memory")

// ---------------- sin/cos table (reference op order) -------------------------
__global__ __launch_bounds__(256) void sincos_table(
    float* __restrict__ st, float* __restrict__ ct)
{
    int idx = blockIdx.x * blockDim.x + threadIdx.x;
    if (idx >= T_LEN * 64) return;
    int i = idx & 63;
    int t = idx >> 6;
    float ts  = powf(10000.0f, (float)i * (1.0f / 64.0f));
    float ang = (float)t / ts;
    float s, c;
    sincosf(ang, &s, &c);
    st[idx] = s;
    ct[idx] = c;
}

// ---------------- elementwise fp32 -> fp16 hi/lo -----------------------------
__global__ __launch_bounds__(256) void split_ew_h(
    const float* __restrict__ src, __half* __restrict__ dH,
    __half* __restrict__ dL, int total)
{
    int idx = blockIdx.x * blockDim.x + threadIdx.x;
    if (idx >= total) return;
    float v = src[idx];
    __half h = __float2half_rn(v);
    dH[idx] = h;
    dL[idx] = __float2half_rn(v - __half2float(h));
}

// ---------------- transpose: src[K][N] fp32 -> dst[N][K] fp16 ----------------
__global__ __launch_bounds__(256) void transpose_h(
    const float* __restrict__ src, __half* __restrict__ dst, int K, int N)
{
    __shared__ float t[32][33];
    const int n0 = blockIdx.x * 32;
    const int k0 = blockIdx.y * 32;
    const int tx = threadIdx.x & 31;
    const int ty = threadIdx.x >> 5;
#pragma unroll
    for (int i = 0; i < 4; i++)
        t[ty + i * 8][tx] = src[(size_t)(k0 + ty + i * 8) * N + n0 + tx];
    __syncthreads();
#pragma unroll
    for (int i = 0; i < 4; i++)
        dst[(size_t)(n0 + ty + i * 8) * K + k0 + tx] =
            __float2half_rn(t[tx][ty + i * 8]);
}

// ============================================================================
// fp16 2-pass GEMM: C[M,N] = (Ah + Al)[M,K] * BT[N,K]^T, fp32 accumulate.
// cp.async 3-stage pipeline. OUT_MODE=0: fp32 C. OUT_MODE=1: single fp16 CH.
// ============================================================================
#define BM 128
#define BN 128
#define BK 32
#define KST 40
#define TILE_ELEMS (BM * KST)
#define STAGE_ELEMS (3 * TILE_ELEMS)
#define NSTAGE 3
#define GEMM_SMEM_BYTES (NSTAGE * STAGE_ELEMS * 2)   // 92160 B

template<int OUT_MODE>
__global__ __launch_bounds__(256) void gemm_h2(
    const __half* __restrict__ AH, const __half* __restrict__ AL,
    const __half* __restrict__ BT,
    float* __restrict__ C, __half* __restrict__ CH, int M, int N, int K)
{
    extern __shared__ __half smg[];

    const int tid  = threadIdx.x;
    const int lane = tid & 31;
    const int warp = tid >> 5;
    const int wm = (warp >> 2) * 64;
    const int wn = (warp & 3) * 32;
    const int row0 = blockIdx.y * BM;
    const int col0 = blockIdx.x * BN;

    const int lr  = tid >> 1;
    const int lc0 = (tid & 1) * 16;

    float acc[4][4][4];
#pragma unroll
    for (int a = 0; a < 4; a++)
#pragma unroll
        for (int b = 0; b < 4; b++)
#pragma unroll
            for (int cc = 0; cc < 4; cc++) acc[a][b][cc] = 0.f;

    const __half* srcs[3] = {
        AH + (size_t)(row0 + lr) * K + lc0,
        AL + (size_t)(row0 + lr) * K + lc0,
        BT + (size_t)(col0 + lr) * K + lc0 };
    const uint32_t sdst0 = sptr(smg) + (lr * KST + lc0) * 2;

    auto stage_issue = [&](int it, int stg) {
        const int kk = it * BK;
        const uint32_t sbase = sdst0 + stg * (STAGE_ELEMS * 2);
#pragma unroll
        for (int t3 = 0; t3 < 3; t3++) {
            const __half* s = srcs[t3] + kk;
            uint32_t d = sbase + t3 * (TILE_ELEMS * 2);
            CP_ASYNC16(d,      s);
            CP_ASYNC16(d + 16, s + 8);
        }
        CP_COMMIT();
    };

    const int KITER = K / BK;
    stage_issue(0, 0);
    stage_issue(1, 1);

    for (int it = 0; it < KITER; it++) {
        if (it + 1 < KITER) { CP_WAIT(1); } else { CP_WAIT(0); }
        __syncthreads();
        if (it + 2 < KITER) stage_issue(it + 2, (it + 2) % NSTAGE);

        const __half* st = smg + (it % NSTAGE) * STAGE_ELEMS;
        const __half* aHb = st;
        const __half* aLb = st + TILE_ELEMS;
        const __half* bTb = st + 2 * TILE_ELEMS;
#pragma unroll
        for (int g = 0; g < 2; g++) {
            const int arow = wm + (lane & 15);
            const int acol = g * 16 + (lane >> 4) * 8;
            const int brow = wn + (lane & 7);
            const int bcol = g * 16 + ((lane >> 3) & 1) * 8;
            uint32_t aHadr = sptr(aHb + arow * KST + acol);
            uint32_t aLadr = sptr(aLb + arow * KST + acol);
            uint32_t bTadr = sptr(bTb + brow * KST + bcol);

            uint32_t aH[4][4], aL[4][4], bT[4][2];
#pragma unroll
            for (int mf = 0; mf < 4; mf++) {
                ldsm4(aH[mf][0], aH[mf][1], aH[mf][2], aH[mf][3],
                      aHadr + mf * 16 * KST * 2);
                ldsm4(aL[mf][0], aL[mf][1], aL[mf][2], aL[mf][3],
                      aLadr + mf * 16 * KST * 2);
            }
#pragma unroll
            for (int nf = 0; nf < 4; nf++)
                ldsm2(bT[nf][0], bT[nf][1], bTadr + nf * 8 * KST * 2);
#pragma unroll
            for (int mf = 0; mf < 4; mf++)
#pragma unroll
                for (int nf = 0; nf < 4; nf++) {
                    mma_hf(acc[mf][nf], aH[mf][0], aH[mf][1], aH[mf][2], aH[mf][3],
                           bT[nf][0], bT[nf][1]);
                    mma_hf(acc[mf][nf], aL[mf][0], aL[mf][1], aL[mf][2], aL[mf][3],
                           bT[nf][0], bT[nf][1]);
                }
        }
    }

#pragma unroll
    for (int mf = 0; mf < 4; mf++)
#pragma unroll
        for (int nf = 0; nf < 4; nf++) {
            int m = row0 + wm + mf * 16 + (lane >> 2);
            int n = col0 + wn + nf * 8 + (lane & 3) * 2;
            if (OUT_MODE == 0) {
                *(float2*)(C + (size_t)m * N + n) =
                    make_float2(acc[mf][nf][0], acc[mf][nf][1]);
                *(float2*)(C + (size_t)(m + 8) * N + n) =
                    make_float2(acc[mf][nf][2], acc[mf][nf][3]);
            } else {
                *(uint32_t*)(CH + (size_t)m * N + n) =
                    packhf(acc[mf][nf][0], acc[mf][nf][1]);
                *(uint32_t*)(CH + (size_t)(m + 8) * N + n) =
                    packhf(acc[mf][nf][2], acc[mf][nf][3]);
            }
        }
}

// ---------------- RoPE (table) -> Q fp16 hi/lo -------------------------------
__global__ __launch_bounds__(256) void rope_q(
    const float* __restrict__ src, const float* __restrict__ st,
    const float* __restrict__ ct, __half* __restrict__ dH,
    __half* __restrict__ dL)
{
    int idx = blockIdx.x * blockDim.x + threadIdx.x;
    if (idx >= T_LEN * NH * 64) return;
    int i  = idx & 63;
    int hd = (idx >> 6) % NH;
    int t  = idx / (64 * NH);

    float s = st[t * 64 + i];
    float c = ct[t * 64 + i];

    size_t base = ((size_t)t * NH + hd) * HD + i;
    float a = src[base];
    float b = src[base + 64];
    float r0 = a * c - b * s;
    float r1 = b * c + a * s;

    __half h0 = __float2half_rn(r0);
    __half h1 = __float2half_rn(r1);
    dH[base]      = h0;
    dH[base + 64] = h1;
    dL[base]      = __float2half_rn(r0 - __half2float(h0));
    dL[base + 64] = __float2half_rn(r1 - __half2float(h1));
}

// ---------------- RoPE (table) -> K single fp16 ------------------------------
__global__ __launch_bounds__(256) void rope_k(
    const float* __restrict__ src, const float* __restrict__ st,
    const float* __restrict__ ct, __half* __restrict__ dst)
{
    int idx = blockIdx.x * blockDim.x + threadIdx.x;
    if (idx >= T_LEN * NKV * 64) return;
    int i  = idx & 63;
    int hd = (idx >> 6) % NKV;
    int t  = idx / (64 * NKV);

    float s = st[t * 64 + i];
    float c = ct[t * 64 + i];

    size_t base = ((size_t)t * NKV + hd) * HD + i;
    float a = src[base];
    float b = src[base + 64];
    dst[base]      = __float2half_rn(a * c - b * s);
    dst[base + 64] = __float2half_rn(b * c + a * s);
}

// ============================================================================
// Attention, fp16 2-pass: S = (Qh+Ql)·K16; O += (Ph+Pl)·V16. fp32 softmax.
// 4 warps x 16q, 64q x 64k tiles. Epilogue: fp16 hi/lo (out-proj format).
// ============================================================================
#define QKSTRIDE 136
#define VTSTRIDE 72
#define SM_QH 0
#define SM_QL 8704
#define SM_K  17408
#define SM_V  26112
#define ATTN_SMEM_BYTES ((26112 + 128 * VTSTRIDE) * 2)   // 70656 B

__global__ __launch_bounds__(128) void attn_mma(
    const __half* __restrict__ QH, const __half* __restrict__ QL,
    const __half* __restrict__ Km, const __half* __restrict__ Vm,
    __half* __restrict__ attH, __half* __restrict__ attL)
{
    extern __shared__ __half sa[];
    __half* QsH = sa + SM_QH;
    __half* QsL = sa + SM_QL;
    __half* Ks  = sa + SM_K;
    __half* Vt  = sa + SM_V;

    const int qt = blockIdx.x;
    const int h  = blockIdx.y;
    const int n  = blockIdx.z;
    const int kvh = h >> 2;
    const int p0  = qt * 64;
    const int tid  = threadIdx.x;
    const int lane = tid & 31;
    const int warp = tid >> 5;
    const int wq   = warp * 16;

    {
        int row = tid >> 1;
        int dh  = (tid & 1) * 64;
        size_t src = ((size_t)(n * WW + p0 + row)) * C_DIM + h * HD + dh;
        int dst = row * QKSTRIDE + dh;
#pragma unroll
        for (int i = 0; i < 8; i++) {
            *(uint4*)(QsH + dst + i * 8) = *(const uint4*)(QH + src + i * 8);
            *(uint4*)(QsL + dst + i * 8) = *(const uint4*)(QL + src + i * 8);
        }
    }

    float o[16][4];
#pragma unroll
    for (int dt = 0; dt < 16; dt++)
#pragma unroll
        for (int c = 0; c < 4; c++) o[dt][c] = 0.f;
    float m0 = -1e30f, m1 = -1e30f, l0 = 0.f, l1 = 0.f;

    const float SCL = 0.08838834764831845f * 1.4426950408889634f;
    const int kt0 = (n == 0) ? (16 - qt) : 0;

    for (int kt = kt0; kt <= 16; kt++) {
        const int jt  = p0 + kt * 64;
        const int ktg0 = (n - 1) * WW + jt;
        __syncthreads();

        {
            int key = tid >> 1;
            int dh  = (tid & 1) * 64;
            size_t src = ((size_t)(ktg0 + key)) * (NKV * HD) + kvh * HD + dh;
            int dst = key * QKSTRIDE + dh;
#pragma unroll
            for (int i = 0; i < 8; i++)
                *(uint4*)(Ks + dst + i * 8) = *(const uint4*)(Km + src + i * 8);
        }
        {
            int key = tid & 63;
            int dh  = (tid >> 6) * 64;
            size_t src = ((size_t)(ktg0 + key)) * (NKV * HD) + kvh * HD + dh;
#pragma unroll
            for (int i = 0; i < 8; i++) {
                uint4 vv = *(const uint4*)(Vm + src + i * 8);
                const __half* pv = (const __half*)&vv;
#pragma unroll
                for (int e = 0; e < 8; e++)
                    Vt[(dh + i * 8 + e) * VTSTRIDE + key] = pv[e];
            }
        }
        __syncthreads();

        float s[8][4];
#pragma unroll
        for (int nt = 0; nt < 8; nt++)
#pragma unroll
            for (int c = 0; c < 4; c++) s[nt][c] = 0.f;

        const int arow = wq + (lane & 15);
        const int acolo = (lane >> 4) * 8;
        const int brow = lane & 7;
        const int bcolo = ((lane >> 3) & 1) * 8;
#pragma unroll
        for (int ks = 0; ks < 8; ks++) {
            uint32_t aH0, aH1, aH2, aH3, aL0, aL1, aL2, aL3;
            ldsm4(aH0, aH1, aH2, aH3,
                  sptr(QsH + arow * QKSTRIDE + ks * 16 + acolo));
            ldsm4(aL0, aL1, aL2, aL3,
                  sptr(QsL + arow * QKSTRIDE + ks * 16 + acolo));
#pragma unroll
            for (int nt = 0; nt < 8; nt++) {
                uint32_t b0, b1;
                ldsm2(b0, b1,
                      sptr(Ks + (nt * 8 + brow) * QKSTRIDE + ks * 16 + bcolo));
                mma_hf(s[nt], aH0, aH1, aH2, aH3, b0, b1);
                mma_hf(s[nt], aL0, aL1, aL2, aL3, b0, b1);
            }
        }

#pragma unroll
        for (int nt = 0; nt < 8; nt++)
#pragma unroll
            for (int c = 0; c < 4; c++) s[nt][c] *= SCL;

        if (kt == 0 || kt == 16) {
            const bool upper = (kt == 16);
            const int r0 = p0 + wq + (lane >> 2);
            const int r1 = r0 + 8;
#pragma unroll
            for (int nt = 0; nt < 8; nt++) {
                int j0 = jt + nt * 8 + (lane & 3) * 2;
#pragma unroll
                for (int c = 0; c < 2; c++) {
                    int j = j0 + c;
                    bool v0 = upper ? (j <= r0 + WW) : (j >= r0);
                    bool v1 = upper ? (j <= r1 + WW) : (j >= r1);
                    if (!v0) s[nt][c]     = -1e30f;
                    if (!v1) s[nt][c + 2] = -1e30f;
                }
            }
        }

        float nm0 = -1e30f, nm1 = -1e30f;
#pragma unroll
        for (int nt = 0; nt < 8; nt++) {
            nm0 = fmaxf(nm0, fmaxf(s[nt][0], s[nt][1]));
            nm1 = fmaxf(nm1, fmaxf(s[nt][2], s[nt][3]));
        }
#pragma unroll
        for (int off = 1; off <= 2; off <<= 1) {
            nm0 = fmaxf(nm0, __shfl_xor_sync(0xffffffffu, nm0, off));
            nm1 = fmaxf(nm1, __shfl_xor_sync(0xffffffffu, nm1, off));
        }
        nm0 = fmaxf(nm0, m0);
        nm1 = fmaxf(nm1, m1);
        float sc0 = ex2(m0 - nm0);
        float sc1 = ex2(m1 - nm1);

        uint32_t pH[8][2], pL[8][2];
        float ls0 = 0.f, ls1 = 0.f;
#pragma unroll
        for (int nt = 0; nt < 8; nt++) {
            float p00 = ex2(s[nt][0] - nm0);
            float p01 = ex2(s[nt][1] - nm0);
            float p10 = ex2(s[nt][2] - nm1);
            float p11 = ex2(s[nt][3] - nm1);
            ls0 += p00 + p01;
            ls1 += p10 + p11;
            pH[nt][0] = packhf(p00, p01);
            pH[nt][1] = packhf(p10, p11);
            __half2 h0 = *(__half2*)&pH[nt][0];
            __half2 h1 = *(__half2*)&pH[nt][1];
            pL[nt][0] = packhf(p00 - __half2float(h0.x),
                               p01 - __half2float(h0.y));
            pL[nt][1] = packhf(p10 - __half2float(h1.x),
                               p11 - __half2float(h1.y));
        }
#pragma unroll
        for (int off = 1; off <= 2; off <<= 1) {
            ls0 += __shfl_xor_sync(0xffffffffu, ls0, off);
            ls1 += __shfl_xor_sync(0xffffffffu, ls1, off);
        }
        l0 = l0 * sc0 + ls0;
        l1 = l1 * sc1 + ls1;
        m0 = nm0;
        m1 = nm1;
#pragma unroll
        for (int dt = 0; dt < 16; dt++) {
            o[dt][0] *= sc0; o[dt][1] *= sc0;
            o[dt][2] *= sc1; o[dt][3] *= sc1;
        }

#pragma unroll
        for (int ks = 0; ks < 4; ks++) {
            uint32_t aH0 = pH[2 * ks][0],     aH1 = pH[2 * ks][1];
            uint32_t aH2 = pH[2 * ks + 1][0], aH3 = pH[2 * ks + 1][1];
            uint32_t aL0 = pL[2 * ks][0],     aL1 = pL[2 * ks][1];
            uint32_t aL2 = pL[2 * ks + 1][0], aL3 = pL[2 * ks + 1][1];
#pragma unroll
            for (int dt = 0; dt < 16; dt++) {
                uint32_t b0, b1;
                ldsm2(b0, b1,
                      sptr(Vt + (dt * 8 + brow) * VTSTRIDE + ks * 16 + bcolo));
                mma_hf(o[dt], aH0, aH1, aH2, aH3, b0, b1);
                mma_hf(o[dt], aL0, aL1, aL2, aL3, b0, b1);
            }
        }
    }

    // ---- normalize + split-store fp16 hi/lo ----
    float inv0 = 1.f / l0;
    float inv1 = 1.f / l1;
    const int r0 = n * WW + p0 + wq + (lane >> 2);
#pragma unroll
    for (int dt = 0; dt < 16; dt++) {
        int col = h * HD + dt * 8 + (lane & 3) * 2;
#pragma unroll
        for (int half = 0; half < 2; half++) {
            float v0 = o[dt][half * 2 + 0] * (half ? inv1 : inv0);
            float v1 = o[dt][half * 2 + 1] * (half ? inv1 : inv0);
            uint32_t hh = packhf(v0, v1);
            __half2 hv = *(__half2*)&hh;
            uint32_t ll = packhf(v0 - __half2float(hv.x),
                                 v1 - __half2float(hv.y));
            size_t off = (size_t)(r0 + half * 8) * C_DIM + col;
            *(uint32_t*)(attH + off) = hh;
            *(uint32_t*)(attL + off) = ll;
        }
    }
}

// ---------------- launch ----------------------------------------------------
extern "C" void kernel_launch(void* const* d_in, const int* in_sizes, int n_in,
                              void* d_out, int out_size)
{
    (void)in_sizes; (void)n_in; (void)out_size;
    const float* x  = (const float*)d_in[0];
    const float* qw = (const float*)d_in[1];
    const float* kw = (const float*)d_in[2];
    const float* vw = (const float*)d_in[3];
    const float* ow = (const float*)d_in[4];
    float* out = (float*)d_out;

    float *Qp, *Kp, *sinp, *cosp;
    __half *xH, *xL, *QHp, *QLp, *Ksp, *Vsp, *atH, *atL, *qwT, *kwT, *vwT, *owT;
    cudaGetSymbolAddress((void**)&Qp, g_Q);
    cudaGetSymbolAddress((void**)&Kp, g_K);
    cudaGetSymbolAddress((void**)&sinp, g_sin);
    cudaGetSymbolAddress((void**)&cosp, g_cos);
    cudaGetSymbolAddress((void**)&xH, g_xH);
    cudaGetSymbolAddress((void**)&xL, g_xL);
    cudaGetSymbolAddress((void**)&QHp, g_QH);
    cudaGetSymbolAddress((void**)&QLp, g_QL);
    cudaGetSymbolAddress((void**)&Ksp, g_Ks);
    cudaGetSymbolAddress((void**)&Vsp, g_Vs);
    cudaGetSymbolAddress((void**)&atH, g_attH);
    cudaGetSymbolAddress((void**)&atL, g_attL);
    cudaGetSymbolAddress((void**)&qwT, g_qwT);
    cudaGetSymbolAddress((void**)&kwT, g_kwT);
    cudaGetSymbolAddress((void**)&vwT, g_vwT);
    cudaGetSymbolAddress((void**)&owT, g_owT);

    cudaFuncSetAttribute(gemm_h2<0>,
                         cudaFuncAttributeMaxDynamicSharedMemorySize, GEMM_SMEM_BYTES);
    cudaFuncSetAttribute(gemm_h2<1>,
                         cudaFuncAttributeMaxDynamicSharedMemorySize, GEMM_SMEM_BYTES);
    cudaFuncSetAttribute(attn_mma,
                         cudaFuncAttributeMaxDynamicSharedMemorySize, ATTN_SMEM_BYTES);

    dim3 thr(256);
    // preprocessing (launch 5 = Q GEMM for the ncu capture window)
    split_ew_h<<<(T_LEN * C_DIM) / 256, 256>>>(x, xH, xL, T_LEN * C_DIM);
    sincos_table<<<(T_LEN * 64) / 256, 256>>>(sinp, cosp);
    transpose_h<<<dim3(C_DIM / 32, C_DIM / 32), thr>>>(qw, qwT, C_DIM, C_DIM);
    transpose_h<<<dim3((NKV * HD) / 32, C_DIM / 32), thr>>>(kw, kwT, C_DIM, NKV * HD);

    // launch 5: Q projection (profiled)
    gemm_h2<0><<<dim3(C_DIM / BN, T_LEN / BM), thr, GEMM_SMEM_BYTES>>>(
        xH, xL, qwT, Qp, nullptr, T_LEN, C_DIM, C_DIM);
    transpose_h<<<dim3((NKV * HD) / 32, C_DIM / 32), thr>>>(vw, vwT, C_DIM, NKV * HD);
    gemm_h2<0><<<dim3((NKV * HD) / BN, T_LEN / BM), thr, GEMM_SMEM_BYTES>>>(
        xH, xL, kwT, Kp, nullptr, T_LEN, NKV * HD, C_DIM);
    gemm_h2<1><<<dim3((NKV * HD) / BN, T_LEN / BM), thr, GEMM_SMEM_BYTES>>>(
        xH, xL, vwT, nullptr, Vsp, T_LEN, NKV * HD, C_DIM);

    // RoPE (table-driven)
    rope_q<<<(T_LEN * NH  * 64) / 256, 256>>>(Qp, sinp, cosp, QHp, QLp);
    rope_k<<<(T_LEN * NKV * 64) / 256, 256>>>(Kp, sinp, cosp, Ksp);

    // attention (fp16 2-pass)
    attn_mma<<<dim3(WW / 64, NH, NB), dim3(128), ATTN_SMEM_BYTES>>>(
        QHp, QLp, Ksp, Vsp, atH, atL);

    // out projection (fp16 2-pass)
    transpose_h<<<dim3(C_DIM / 32, C_DIM / 32), thr>>>(ow, owT, C_DIM, C_DIM);
    gemm_h2<0><<<dim3(C_DIM / BN, T_LEN / BM), thr, GEMM_SMEM_BYTES>>>(
        atH, atL, owT, out, nullptr, T_LEN, C_DIM, C_DIM);
}